// round 11
// baseline (speedup 1.0000x reference)
#include <cuda_runtime.h>
#include <cuda_bf16.h>
#include <math.h>
#include <stdint.h>

#define NUM_NODES 262144
#define HID 256
#define NGRAPH 1024
#define NT256 (NUM_NODES / 256)    // 1024 tiles of 256 nodes
#define NSM 148

// ---------------- scratch (static device globals) ----------------
__device__ float g_sw[NGRAPH];     // segment sum of exp(score)
// W1^T packed b-frag quads: [kstep 0..15][nt 0..15][lane 0..31][bh0,bh1,bl0,bl1]
__device__ uint32_t g_B[16 * 16 * 32 * 4];   // 32768 u32 = 128KB

__device__ __forceinline__ uint32_t smem_u32(const void* p) {
    uint32_t a;
    asm("{ .reg .u64 t; cvta.to.shared.u64 t, %1; cvt.u32.u64 %0, t; }" : "=r"(a) : "l"(p));
    return a;
}
__device__ __forceinline__ void mma_bf16(float* c, const uint32_t* a,
                                         uint32_t b0, uint32_t b1) {
    asm volatile(
        "mma.sync.aligned.m16n8k16.row.col.f32.bf16.bf16.f32 "
        "{%0,%1,%2,%3}, {%4,%5,%6,%7}, {%8,%9}, {%0,%1,%2,%3};"
        : "+f"(c[0]), "+f"(c[1]), "+f"(c[2]), "+f"(c[3])
        : "r"(a[0]), "r"(a[1]), "r"(a[2]), "r"(a[3]), "r"(b0), "r"(b1));
}
__device__ __forceinline__ void ldsm_x4(uint32_t* a, uint32_t addr) {
    asm volatile("ldmatrix.sync.aligned.m8n8.x4.shared.b16 {%0,%1,%2,%3}, [%4];"
        : "=r"(a[0]), "=r"(a[1]), "=r"(a[2]), "=r"(a[3]) : "r"(addr));
}
__device__ __forceinline__ float tanh_fast(float h) {
    float t;
    asm("tanh.approx.f32 %0, %1;" : "=f"(t) : "f"(h));
    return t;
}

// ---------------- prep: W1^T -> packed split-bf16 b-frag quads -------------
__global__ void prep_kernel(const float* __restrict__ W1) {  // W1[256][128]
    int i = blockIdx.x * 256 + threadIdx.x;   // 0..8191
    if (i >= 8192) return;
    int l = i & 31, nt = (i >> 5) & 15, ks = i >> 9;
    int gr = l >> 2, qc = l & 3;
    int n = nt * 8 + gr;
    int kp0 = (ks >> 2) * 32 + (ks & 3) * 8 + qc;
    int kp1 = kp0 + 4;
    float w00 = W1[(2 * kp0) * 128 + n],     w01 = W1[(2 * kp0 + 1) * 128 + n];
    float w10 = W1[(2 * kp1) * 128 + n],     w11 = W1[(2 * kp1 + 1) * 128 + n];
    __nv_bfloat16 h00 = __float2bfloat16(w00), h01 = __float2bfloat16(w01);
    __nv_bfloat16 h10 = __float2bfloat16(w10), h11 = __float2bfloat16(w11);
    __nv_bfloat16 l00 = __float2bfloat16(w00 - __bfloat162float(h00));
    __nv_bfloat16 l01 = __float2bfloat16(w01 - __bfloat162float(h01));
    __nv_bfloat16 l10 = __float2bfloat16(w10 - __bfloat162float(h10));
    __nv_bfloat16 l11 = __float2bfloat16(w11 - __bfloat162float(h11));
    uint32_t* dst = g_B + i * 4;
    dst[0] = (uint32_t)*(unsigned short*)&h00 | ((uint32_t)*(unsigned short*)&h01 << 16);
    dst[1] = (uint32_t)*(unsigned short*)&h10 | ((uint32_t)*(unsigned short*)&h11 << 16);
    dst[2] = (uint32_t)*(unsigned short*)&l00 | ((uint32_t)*(unsigned short*)&l01 << 16);
    dst[3] = (uint32_t)*(unsigned short*)&l10 | ((uint32_t)*(unsigned short*)&l11 << 16);
}

__global__ void init_kernel(float* __restrict__ out) {
    int i = blockIdx.x * blockDim.x + threadIdx.x;
    if (i < NGRAPH * HID) out[i] = 0.f;
    if (i < NGRAPH) g_sw[i] = 0.f;
}

// ---------------------------------------------------------------------------
// fused score+pool: 256-node tiles, warp owns 32 rows x 128 cols (2 m-frags).
// Halves per-row B smem traffic vs 128-tile. A loads via ldmatrix.x4,
// chunk loads in two 8-float4 batches (no reg prefetch; MMA of other warps
// hides LDG). Epilogue tanh.approx + fused L2-hot pooling.
// dyn smem u32: B quads [0, 32768) ; A slabs: warp w at 32768 + w*2304
// (hi [32][36], lo +1152).
// ---------------------------------------------------------------------------
#define A_OFF 32768
#define A_WSZ 2304
#define A_PAD 36

__global__ void __launch_bounds__(256, 1) score_kernel(
    const float* __restrict__ x,
    const int* __restrict__ batch,
    const float* __restrict__ b1,
    const float* __restrict__ W2,
    const float* __restrict__ b2,
    float* __restrict__ out)
{
    extern __shared__ uint32_t sm[];
    __shared__ float sb1[128], sW2[128];

    const int tid = threadIdx.x, w = tid >> 5, l = tid & 31;
    const int gr = l >> 2, qc = l & 3;

    {   // B copy: 32768 u32 = 8192 float4
        const float4* src = (const float4*)g_B;
        float4* dst = (float4*)sm;
        #pragma unroll
        for (int i = 0; i < 32; ++i) dst[tid + i * 256] = src[tid + i * 256];
    }
    if (tid < 128) { sb1[tid] = b1[tid]; sW2[tid] = W2[tid]; }
    __syncthreads();

    const float b2v = __ldg(&b2[0]);
    uint32_t* const Ahi = sm + A_OFF + w * A_WSZ;
    uint32_t* const Alo = Ahi + 1152;
    const uint32_t a_hi_base = smem_u32(Ahi) + ((l & 15) * A_PAD + (l >> 4) * 4) * 4;
    const uint32_t a_lo_base = a_hi_base + 1152 * 4;
    const uint4* const Bq = (const uint4*)sm;     // [kstep][nt][lane]
    const float4* xg = (const float4*)x;          // [node][64]

    for (int t = blockIdx.x; t < NT256; t += NSM) {
        const int rbase = t * 256 + w * 32;

        float acc0[16][4], acc1[16][4];
        #pragma unroll
        for (int nt = 0; nt < 16; ++nt)
            #pragma unroll
            for (int j = 0; j < 4; ++j) { acc0[nt][j] = 0.f; acc1[nt][j] = 0.f; }

        for (int c = 0; c < 4; ++c) {
            __syncwarp();
            #pragma unroll
            for (int half = 0; half < 2; ++half) {
                float4 v[8];
                #pragma unroll
                for (int i = 0; i < 8; ++i) {
                    int f = (half * 8 + i) * 32 + l;
                    v[i] = xg[(size_t)(rbase + (f >> 4)) * 64 + c * 16 + (f & 15)];
                }
                #pragma unroll
                for (int i = 0; i < 8; ++i) {
                    int f = (half * 8 + i) * 32 + l;
                    int r = f >> 4, q = f & 15;
                    __nv_bfloat162 h01 = __float22bfloat162_rn(make_float2(v[i].x, v[i].y));
                    __nv_bfloat162 h23 = __float22bfloat162_rn(make_float2(v[i].z, v[i].w));
                    float2 f01 = __bfloat1622float2(h01);
                    float2 f23 = __bfloat1622float2(h23);
                    __nv_bfloat162 l01 = __float22bfloat162_rn(make_float2(v[i].x - f01.x, v[i].y - f01.y));
                    __nv_bfloat162 l23 = __float22bfloat162_rn(make_float2(v[i].z - f23.x, v[i].w - f23.y));
                    uint64_t hv = (uint64_t)(*(uint32_t*)&h01) | ((uint64_t)(*(uint32_t*)&h23) << 32);
                    uint64_t lv = (uint64_t)(*(uint32_t*)&l01) | ((uint64_t)(*(uint32_t*)&l23) << 32);
                    *(uint64_t*)(Ahi + r * A_PAD + q * 2) = hv;   // STS.64
                    *(uint64_t*)(Alo + r * A_PAD + q * 2) = lv;
                }
            }
            __syncwarp();
            for (int k16 = 0; k16 < 4; ++k16) {
                uint32_t ah0[4], ah1[4], al0[4], al1[4];
                ldsm_x4(ah0, a_hi_base + k16 * 32);
                ldsm_x4(ah1, a_hi_base + 2304 + k16 * 32);    // rows 16-31
                ldsm_x4(al0, a_lo_base + k16 * 32);
                ldsm_x4(al1, a_lo_base + 2304 + k16 * 32);
                const uint4* Bk = Bq + ((c * 4 + k16) * 16) * 32 + l;
                #pragma unroll
                for (int nt = 0; nt < 16; ++nt) {
                    uint4 q = Bk[nt * 32];          // LDS.128, conflict-free
                    mma_bf16(acc0[nt], ah0, q.x, q.y);
                    mma_bf16(acc0[nt], ah0, q.z, q.w);
                    mma_bf16(acc0[nt], al0, q.x, q.y);
                    mma_bf16(acc1[nt], ah1, q.x, q.y);
                    mma_bf16(acc1[nt], ah1, q.z, q.w);
                    mma_bf16(acc1[nt], al1, q.x, q.y);
                }
            }
        }

        // epilogue: 4 row-group partials. pr[0]=rows 0-7, [1]=8-15, [2]=16-23,
        // [3]=24-31 (after quad reduce, all 4 quad lanes hold the value).
        float pr[4] = {0.f, 0.f, 0.f, 0.f};
        #pragma unroll
        for (int nt = 0; nt < 16; ++nt) {
            #pragma unroll
            for (int j = 0; j < 2; ++j) {
                int col = nt * 8 + qc * 2 + j;
                float bb = sb1[col], ww = sW2[col];
                pr[0] = fmaf(tanh_fast(acc0[nt][j] + bb), ww, pr[0]);
                pr[1] = fmaf(tanh_fast(acc0[nt][2 + j] + bb), ww, pr[1]);
                pr[2] = fmaf(tanh_fast(acc1[nt][j] + bb), ww, pr[2]);
                pr[3] = fmaf(tanh_fast(acc1[nt][2 + j] + bb), ww, pr[3]);
            }
        }
        #pragma unroll
        for (int m = 0; m < 4; ++m) {
            pr[m] += __shfl_xor_sync(0xFFFFFFFFu, pr[m], 1);
            pr[m] += __shfl_xor_sync(0xFFFFFFFFu, pr[m], 2);
        }

        // ---- fused pool phase: re-read 32 rows x 256 cols (L2-hot) ----
        float4 accA = make_float4(0.f, 0.f, 0.f, 0.f);
        float4 accB = make_float4(0.f, 0.f, 0.f, 0.f);
        float wsum = 0.f;
        int curb = __ldg(&batch[rbase]);
        #pragma unroll
        for (int r = 0; r < 32; ++r) {
            float sc;
            { float pv = pr[r >> 3]; sc = __shfl_sync(0xFFFFFFFFu, pv, (r & 7) * 4); }
            float wv = __expf(sc + b2v);
            int b = __ldg(&batch[rbase + r]);
            if (b != curb) {
                float* o = &out[curb * HID + l * 4];
                atomicAdd(o + 0, accA.x); atomicAdd(o + 1, accA.y);
                atomicAdd(o + 2, accA.z); atomicAdd(o + 3, accA.w);
                float* o2 = o + 128;
                atomicAdd(o2 + 0, accB.x); atomicAdd(o2 + 1, accB.y);
                atomicAdd(o2 + 2, accB.z); atomicAdd(o2 + 3, accB.w);
                if (l == 0) atomicAdd(&g_sw[curb], wsum);
                accA = make_float4(0.f, 0.f, 0.f, 0.f);
                accB = make_float4(0.f, 0.f, 0.f, 0.f);
                wsum = 0.f;
                curb = b;
            }
            wsum += wv;
            float4 xa = xg[(size_t)(rbase + r) * 64 + l];
            float4 xb = xg[(size_t)(rbase + r) * 64 + 32 + l];
            accA.x = fmaf(xa.x, wv, accA.x); accA.y = fmaf(xa.y, wv, accA.y);
            accA.z = fmaf(xa.z, wv, accA.z); accA.w = fmaf(xa.w, wv, accA.w);
            accB.x = fmaf(xb.x, wv, accB.x); accB.y = fmaf(xb.y, wv, accB.y);
            accB.z = fmaf(xb.z, wv, accB.z); accB.w = fmaf(xb.w, wv, accB.w);
        }
        {
            float* o = &out[curb * HID + l * 4];
            atomicAdd(o + 0, accA.x); atomicAdd(o + 1, accA.y);
            atomicAdd(o + 2, accA.z); atomicAdd(o + 3, accA.w);
            float* o2 = o + 128;
            atomicAdd(o2 + 0, accB.x); atomicAdd(o2 + 1, accB.y);
            atomicAdd(o2 + 2, accB.z); atomicAdd(o2 + 3, accB.w);
            if (l == 0) atomicAdd(&g_sw[curb], wsum);
        }
    }
}

// ---------------- normalize: out[b][h] /= S[b] ----------------
__global__ void norm_kernel(float* __restrict__ out) {
    int i = blockIdx.x * blockDim.x + threadIdx.x;   // 0..262143
    float s = g_sw[i >> 8];
    float inv = (s > 0.f) ? __fdividef(1.f, s) : 0.f;
    out[i] *= inv;
}

extern "C" void kernel_launch(void* const* d_in, const int* in_sizes, int n_in,
                              void* d_out, int out_size) {
    const float* x     = (const float*)d_in[0];
    const int*   batch = (const int*)d_in[1];
    const float* W1    = (const float*)d_in[2];
    const float* b1    = (const float*)d_in[3];
    const float* W2    = (const float*)d_in[4];
    const float* b2    = (const float*)d_in[5];
    float* out = (float*)d_out;

    const int dyn = (A_OFF + 8 * A_WSZ) * 4;   // 131072 + 73728 = 204800 B
    cudaFuncSetAttribute(score_kernel, cudaFuncAttributeMaxDynamicSharedMemorySize, dyn);

    prep_kernel<<<32, 256>>>(W1);
    init_kernel<<<(NGRAPH * HID + 255) / 256, 256>>>(out);
    score_kernel<<<NSM, 256, dyn>>>(x, batch, b1, W2, b2, out);
    norm_kernel<<<NGRAPH * HID / 256, 256>>>(out);
}

// round 13
// speedup vs baseline: 1.2209x; 1.2209x over previous
#include <cuda_runtime.h>
#include <cuda_fp16.h>
#include <math.h>
#include <stdint.h>

#define NUM_NODES 262144
#define HID 256
#define NGRAPH 1024
#define NTILES (NUM_NODES / 128)   // 2048
#define NSM 148

// ---------------- scratch (static device globals) ----------------
__device__ float g_sw[NGRAPH];     // segment sum of exp(score)
// W1^T fp16 b-frags: [kstep 0..15][ntpair 0..7][lane 0..31][b0e,b1e,b0o,b1o]
__device__ uint32_t g_B[16 * 8 * 32 * 4];    // 16384 u32 = 64KB

__device__ __forceinline__ uint32_t smem_u32(const void* p) {
    uint32_t a;
    asm("{ .reg .u64 t; cvta.to.shared.u64 t, %1; cvt.u32.u64 %0, t; }" : "=r"(a) : "l"(p));
    return a;
}
__device__ __forceinline__ void mma_f16(float* c, const uint32_t* a,
                                        uint32_t b0, uint32_t b1) {
    asm volatile(
        "mma.sync.aligned.m16n8k16.row.col.f32.f16.f16.f32 "
        "{%0,%1,%2,%3}, {%4,%5,%6,%7}, {%8,%9}, {%0,%1,%2,%3};"
        : "+f"(c[0]), "+f"(c[1]), "+f"(c[2]), "+f"(c[3])
        : "r"(a[0]), "r"(a[1]), "r"(a[2]), "r"(a[3]), "r"(b0), "r"(b1));
}
__device__ __forceinline__ void ldsm_x4(uint32_t* a, uint32_t addr) {
    asm volatile("ldmatrix.sync.aligned.m8n8.x4.shared.b16 {%0,%1,%2,%3}, [%4];"
        : "=r"(a[0]), "=r"(a[1]), "=r"(a[2]), "=r"(a[3]) : "r"(addr));
}
__device__ __forceinline__ float tanh_fast(float h) {
    float t;
    asm("tanh.approx.f32 %0, %1;" : "=f"(t) : "f"(h));
    return t;
}

// ---------------- prep: W1^T -> fp16 b-frag pair-quads ----------------
// For (kstep ks, lane l): kp = ks*8 + qc (k pair), b0 = W^T[n][2kp,2kp+1],
// b1 = [2(kp+4), ..+1]  (proven R5/R10 mapping). Quad packs nt=2ntp (even)
// then nt=2ntp+1 (odd).
__global__ void prep_kernel(const float* __restrict__ W1) {  // W1[256][128]
    int i = blockIdx.x * 256 + threadIdx.x;   // 0..4095
    if (i >= 4096) return;
    int l = i & 31, ntp = (i >> 5) & 7, ks = i >> 8;   // ks 0..15
    int gr = l >> 2, qc = l & 3;
    int kp = ks * 8 + qc;
    uint32_t q[4];
    #pragma unroll
    for (int e = 0; e < 2; ++e) {
        int n = (2 * ntp + e) * 8 + gr;
        __half2 v0 = __floats2half2_rn(W1[(2 * kp) * 128 + n],
                                       W1[(2 * kp + 1) * 128 + n]);
        __half2 v1 = __floats2half2_rn(W1[(2 * (kp + 4)) * 128 + n],
                                       W1[(2 * (kp + 4) + 1) * 128 + n]);
        q[e * 2]     = *(uint32_t*)&v0;
        q[e * 2 + 1] = *(uint32_t*)&v1;
    }
    ((uint4*)g_B)[i] = make_uint4(q[0], q[1], q[2], q[3]);
}

__global__ void init_kernel(float* __restrict__ out) {
    int i = blockIdx.x * blockDim.x + threadIdx.x;
    if (i < NGRAPH * HID) out[i] = 0.f;
    if (i < NGRAPH) g_sw[i] = 0.f;
}

// ---------------------------------------------------------------------------
// fused score+pool (R10 skeleton, single-term fp16 HMMA). Warp owns 16 rows.
// dyn smem u32: B quads [0, 16384) ; A slabs: warp w at 16384 + w*576
// (16 rows x 36 u32, 144B pitch).
// ---------------------------------------------------------------------------
#define A_OFF 16384
#define A_WSZ 576
#define A_PAD 36

__global__ void __launch_bounds__(256, 1) score_kernel(
    const float* __restrict__ x,
    const int* __restrict__ batch,
    const float* __restrict__ b1,
    const float* __restrict__ W2,
    const float* __restrict__ b2,
    float* __restrict__ out)
{
    extern __shared__ uint32_t sm[];
    __shared__ float sb1[128], sW2[128];

    const int tid = threadIdx.x, w = tid >> 5, l = tid & 31;
    const int gr = l >> 2, qc = l & 3;

    {   // B copy: 16384 u32 = 4096 float4
        const float4* src = (const float4*)g_B;
        float4* dst = (float4*)sm;
        #pragma unroll
        for (int i = 0; i < 16; ++i) dst[tid + i * 256] = src[tid + i * 256];
    }
    if (tid < 128) { sb1[tid] = b1[tid]; sW2[tid] = W2[tid]; }
    __syncthreads();

    const float b2v = __ldg(&b2[0]);
    uint32_t* const Ah = sm + A_OFF + w * A_WSZ;
    const uint32_t a_base = smem_u32(Ah) + ((l & 15) * A_PAD + (l >> 4) * 4) * 4;
    const uint4* const Bq = (const uint4*)sm;     // [kstep][ntp][lane]
    const float4* xg = (const float4*)x;          // [node][64]

    for (int t = blockIdx.x; t < NTILES; t += NSM) {
        const int rbase = t * 128 + w * 16;

        float acc[16][4];
        #pragma unroll
        for (int nt = 0; nt < 16; ++nt)
            #pragma unroll
            for (int j = 0; j < 4; ++j) acc[nt][j] = 0.f;

        float4 v[8];
        #pragma unroll
        for (int i = 0; i < 8; ++i) {
            int f = i * 32 + l;
            v[i] = xg[(size_t)(rbase + (f >> 4)) * 64 + (f & 15)];
        }

        for (int c = 0; c < 4; ++c) {
            __syncwarp();
            #pragma unroll
            for (int i = 0; i < 8; ++i) {
                int f = i * 32 + l;
                int r = f >> 4, q = f & 15;
                __half2 h01 = __floats2half2_rn(v[i].x, v[i].y);
                __half2 h23 = __floats2half2_rn(v[i].z, v[i].w);
                uint64_t hv = (uint64_t)(*(uint32_t*)&h01)
                            | ((uint64_t)(*(uint32_t*)&h23) << 32);
                *(uint64_t*)(Ah + r * A_PAD + q * 2) = hv;    // STS.64
            }
            __syncwarp();
            if (c < 3) {
                #pragma unroll
                for (int i = 0; i < 8; ++i) {
                    int f = i * 32 + l;
                    v[i] = xg[(size_t)(rbase + (f >> 4)) * 64 + (c + 1) * 16 + (f & 15)];
                }
            }
            #pragma unroll
            for (int k16 = 0; k16 < 4; ++k16) {
                uint32_t a[4];
                ldsm_x4(a, a_base + k16 * 32);
                const uint4* Bk = Bq + ((c * 4 + k16) * 8) * 32 + l;
                #pragma unroll
                for (int ntp = 0; ntp < 8; ++ntp) {
                    uint4 q = Bk[ntp * 32];       // LDS.128, conflict-free
                    mma_f16(acc[2 * ntp],     a, q.x, q.y);
                    mma_f16(acc[2 * ntp + 1], a, q.z, q.w);
                }
            }
        }

        // epilogue: row scores via HW tanh; quad xor-reduce leaves p0/p1
        // in all 4 quad lanes.
        float p0 = 0.f, p1 = 0.f;
        #pragma unroll
        for (int nt = 0; nt < 16; ++nt) {
            #pragma unroll
            for (int j = 0; j < 2; ++j) {
                int col = nt * 8 + qc * 2 + j;
                float bb = sb1[col], ww = sW2[col];
                p0 = fmaf(tanh_fast(acc[nt][j] + bb), ww, p0);
                p1 = fmaf(tanh_fast(acc[nt][2 + j] + bb), ww, p1);
            }
        }
        p0 += __shfl_xor_sync(0xFFFFFFFFu, p0, 1);
        p0 += __shfl_xor_sync(0xFFFFFFFFu, p0, 2);
        p1 += __shfl_xor_sync(0xFFFFFFFFu, p1, 1);
        p1 += __shfl_xor_sync(0xFFFFFFFFu, p1, 2);

        // ---- fused pool phase: re-read 16 rows x 256 cols (L2-hot) ----
        float4 accA = make_float4(0.f, 0.f, 0.f, 0.f);
        float4 accB = make_float4(0.f, 0.f, 0.f, 0.f);
        float wsum = 0.f;
        int curb = __ldg(&batch[rbase]);
        #pragma unroll
        for (int r = 0; r < 16; ++r) {
            float sc = (r < 8) ? __shfl_sync(0xFFFFFFFFu, p0, r * 4)
                               : __shfl_sync(0xFFFFFFFFu, p1, (r - 8) * 4);
            float wv = __expf(sc + b2v);
            int b = __ldg(&batch[rbase + r]);
            if (b != curb) {
                float* o = &out[curb * HID + l * 4];
                atomicAdd(o + 0, accA.x); atomicAdd(o + 1, accA.y);
                atomicAdd(o + 2, accA.z); atomicAdd(o + 3, accA.w);
                float* o2 = o + 128;
                atomicAdd(o2 + 0, accB.x); atomicAdd(o2 + 1, accB.y);
                atomicAdd(o2 + 2, accB.z); atomicAdd(o2 + 3, accB.w);
                if (l == 0) atomicAdd(&g_sw[curb], wsum);
                accA = make_float4(0.f, 0.f, 0.f, 0.f);
                accB = make_float4(0.f, 0.f, 0.f, 0.f);
                wsum = 0.f;
                curb = b;
            }
            wsum += wv;
            float4 xa = xg[(size_t)(rbase + r) * 64 + l];
            float4 xb = xg[(size_t)(rbase + r) * 64 + 32 + l];
            accA.x = fmaf(xa.x, wv, accA.x); accA.y = fmaf(xa.y, wv, accA.y);
            accA.z = fmaf(xa.z, wv, accA.z); accA.w = fmaf(xa.w, wv, accA.w);
            accB.x = fmaf(xb.x, wv, accB.x); accB.y = fmaf(xb.y, wv, accB.y);
            accB.z = fmaf(xb.z, wv, accB.z); accB.w = fmaf(xb.w, wv, accB.w);
        }
        {
            float* o = &out[curb * HID + l * 4];
            atomicAdd(o + 0, accA.x); atomicAdd(o + 1, accA.y);
            atomicAdd(o + 2, accA.z); atomicAdd(o + 3, accA.w);
            float* o2 = o + 128;
            atomicAdd(o2 + 0, accB.x); atomicAdd(o2 + 1, accB.y);
            atomicAdd(o2 + 2, accB.z); atomicAdd(o2 + 3, accB.w);
            if (l == 0) atomicAdd(&g_sw[curb], wsum);
        }
    }
}

// ---------------- normalize: out[b][h] /= S[b] ----------------
__global__ void norm_kernel(float* __restrict__ out) {
    int i = blockIdx.x * blockDim.x + threadIdx.x;   // 0..262143
    float s = g_sw[i >> 8];
    float inv = (s > 0.f) ? __fdividef(1.f, s) : 0.f;
    out[i] *= inv;
}

extern "C" void kernel_launch(void* const* d_in, const int* in_sizes, int n_in,
                              void* d_out, int out_size) {
    const float* x     = (const float*)d_in[0];
    const int*   batch = (const int*)d_in[1];
    const float* W1    = (const float*)d_in[2];
    const float* b1    = (const float*)d_in[3];
    const float* W2    = (const float*)d_in[4];
    const float* b2    = (const float*)d_in[5];
    float* out = (float*)d_out;

    const int dyn = (A_OFF + 8 * A_WSZ) * 4;   // 65536 + 18432 = 83968 B
    cudaFuncSetAttribute(score_kernel, cudaFuncAttributeMaxDynamicSharedMemorySize, dyn);

    prep_kernel<<<16, 256>>>(W1);
    init_kernel<<<(NGRAPH * HID + 255) / 256, 256>>>(out);
    score_kernel<<<NSM, 256, dyn>>>(x, batch, b1, W2, b2, out);
    norm_kernel<<<NGRAPH * HID / 256, 256>>>(out);
}

// round 15
// speedup vs baseline: 1.8742x; 1.5351x over previous
#include <cuda_runtime.h>
#include <cuda_fp16.h>
#include <math.h>
#include <stdint.h>

#define NUM_NODES 262144
#define HID 256
#define NGRAPH 1024
#define NTILES (NUM_NODES / 128)   // 2048
#define NSM 148

// ---------------- scratch (static device globals) ----------------
__device__ float g_sw[NGRAPH];     // segment sum of exp(score)
// W1^T fp16 b-frags: [kstep 0..15][ntpair 0..7][lane 0..31][b0e,b1e,b0o,b1o]
__device__ uint32_t g_B[16 * 8 * 32 * 4];    // 16384 u32 = 64KB

__device__ __forceinline__ uint32_t smem_u32(const void* p) {
    uint32_t a;
    asm("{ .reg .u64 t; cvta.to.shared.u64 t, %1; cvt.u32.u64 %0, t; }" : "=r"(a) : "l"(p));
    return a;
}
__device__ __forceinline__ void mma_f16(float* c, const uint32_t* a,
                                        uint32_t b0, uint32_t b1) {
    asm volatile(
        "mma.sync.aligned.m16n8k16.row.col.f32.f16.f16.f32 "
        "{%0,%1,%2,%3}, {%4,%5,%6,%7}, {%8,%9}, {%0,%1,%2,%3};"
        : "+f"(c[0]), "+f"(c[1]), "+f"(c[2]), "+f"(c[3])
        : "r"(a[0]), "r"(a[1]), "r"(a[2]), "r"(a[3]), "r"(b0), "r"(b1));
}
__device__ __forceinline__ void ldsm_x4(uint32_t* a, uint32_t addr) {
    asm volatile("ldmatrix.sync.aligned.m8n8.x4.shared.b16 {%0,%1,%2,%3}, [%4];"
        : "=r"(a[0]), "=r"(a[1]), "=r"(a[2]), "=r"(a[3]) : "r"(addr));
}
__device__ __forceinline__ float tanh_fast(float h) {
    float t;
    asm("tanh.approx.f32 %0, %1;" : "=f"(t) : "f"(h));
    return t;
}

// ---------------- prep: W1^T -> fp16 b-frag pair-quads (R13, proven) -------
__global__ void prep_kernel(const float* __restrict__ W1) {  // W1[256][128]
    int i = blockIdx.x * 256 + threadIdx.x;   // 0..4095
    if (i >= 4096) return;
    int l = i & 31, ntp = (i >> 5) & 7, ks = i >> 8;   // ks 0..15
    int gr = l >> 2, qc = l & 3;
    int kp = ks * 8 + qc;
    uint32_t q[4];
    #pragma unroll
    for (int e = 0; e < 2; ++e) {
        int n = (2 * ntp + e) * 8 + gr;
        __half2 v0 = __floats2half2_rn(W1[(2 * kp) * 128 + n],
                                       W1[(2 * kp + 1) * 128 + n]);
        __half2 v1 = __floats2half2_rn(W1[(2 * (kp + 4)) * 128 + n],
                                       W1[(2 * (kp + 4) + 1) * 128 + n]);
        q[e * 2]     = *(uint32_t*)&v0;
        q[e * 2 + 1] = *(uint32_t*)&v1;
    }
    ((uint4*)g_B)[i] = make_uint4(q[0], q[1], q[2], q[3]);
}

__global__ void init_kernel(float* __restrict__ out) {
    int i = blockIdx.x * blockDim.x + threadIdx.x;
    if (i < NGRAPH * HID) out[i] = 0.f;
    if (i < NGRAPH) g_sw[i] = 0.f;
}

// ---------------------------------------------------------------------------
// fused score+pool. Persistent per-tile A slab (16 rows x 256 fp16 cols,
// 4-chunk layout) -> pool phase reads SMEM, no L2 re-read. Cross-tile
// chunk-0 LDG prefetch hides tile-start DRAM latency.
// dyn smem u32: B quads [0, 16384) ; A slabs: warp w at 16384 + w*2112
// (16 rows x 132 u32 pitch; chunk c at col c*32).
// ---------------------------------------------------------------------------
#define A_OFF 16384
#define A_SLAB 2112
#define A_PITCH 132

__global__ void __launch_bounds__(256, 1) score_kernel(
    const float* __restrict__ x,
    const int* __restrict__ batch,
    const float* __restrict__ b1,
    const float* __restrict__ W2,
    const float* __restrict__ b2,
    float* __restrict__ out)
{
    extern __shared__ uint32_t sm[];
    __shared__ float sb1[128], sW2[128];

    const int tid = threadIdx.x, w = tid >> 5, l = tid & 31;
    const int gr = l >> 2, qc = l & 3;

    {   // B copy: 16384 u32 = 4096 float4
        const float4* src = (const float4*)g_B;
        float4* dst = (float4*)sm;
        #pragma unroll
        for (int i = 0; i < 16; ++i) dst[tid + i * 256] = src[tid + i * 256];
    }
    if (tid < 128) { sb1[tid] = b1[tid]; sW2[tid] = W2[tid]; }
    __syncthreads();

    const float b2v = __ldg(&b2[0]);
    uint32_t* const Ah = sm + A_OFF + w * A_SLAB;
    const uint32_t a_base = smem_u32(Ah) + (l & 15) * (A_PITCH * 4) + (l >> 4) * 16;
    const uint4* const Bq = (const uint4*)sm;     // [kstep][ntp][lane]
    const float4* xg = (const float4*)x;          // [node][64]
    const int upool = (l >> 4) * 32 + 2 * (l & 15);   // pool LDS.64 col offset

    float4 v[8];
    {   // preload chunk 0 of first tile
        const int rb0 = blockIdx.x * 128 + w * 16;
        #pragma unroll
        for (int i = 0; i < 8; ++i) {
            int f = i * 32 + l;
            v[i] = xg[(size_t)(rb0 + (f >> 4)) * 64 + (f & 15)];
        }
    }

    for (int t = blockIdx.x; t < NTILES; t += NSM) {
        const int rbase = t * 128 + w * 16;

        float acc[16][4];
        #pragma unroll
        for (int nt = 0; nt < 16; ++nt)
            #pragma unroll
            for (int j = 0; j < 4; ++j) acc[nt][j] = 0.f;

        for (int c = 0; c < 4; ++c) {
            __syncwarp();
            #pragma unroll
            for (int i = 0; i < 8; ++i) {
                int f = i * 32 + l;
                int r = f >> 4, q = f & 15;
                __half2 h01 = __floats2half2_rn(v[i].x, v[i].y);
                __half2 h23 = __floats2half2_rn(v[i].z, v[i].w);
                uint64_t hv = (uint64_t)(*(uint32_t*)&h01)
                            | ((uint64_t)(*(uint32_t*)&h23) << 32);
                *(uint64_t*)(Ah + r * A_PITCH + c * 32 + q * 2) = hv;  // STS.64
            }
            __syncwarp();
            if (c < 3) {
                #pragma unroll
                for (int i = 0; i < 8; ++i) {
                    int f = i * 32 + l;
                    v[i] = xg[(size_t)(rbase + (f >> 4)) * 64 + (c + 1) * 16 + (f & 15)];
                }
            } else if (t + NSM < NTILES) {
                // cross-tile prefetch: chunk 0 of tile t+NSM
                const int rb2 = (t + NSM) * 128 + w * 16;
                #pragma unroll
                for (int i = 0; i < 8; ++i) {
                    int f = i * 32 + l;
                    v[i] = xg[(size_t)(rb2 + (f >> 4)) * 64 + (f & 15)];
                }
            }
            #pragma unroll
            for (int k16 = 0; k16 < 4; ++k16) {
                uint32_t a[4];
                ldsm_x4(a, a_base + c * 128 + k16 * 32);
                const uint4* Bk = Bq + ((c * 4 + k16) * 8) * 32 + l;
                #pragma unroll
                for (int ntp = 0; ntp < 8; ++ntp) {
                    uint4 q = Bk[ntp * 32];       // LDS.128, conflict-free
                    mma_f16(acc[2 * ntp],     a, q.x, q.y);
                    mma_f16(acc[2 * ntp + 1], a, q.z, q.w);
                }
            }
        }

        // epilogue: row scores; quad xor-reduce leaves p0/p1 in all quad lanes
        float p0 = 0.f, p1 = 0.f;
        #pragma unroll
        for (int nt = 0; nt < 16; ++nt) {
            #pragma unroll
            for (int j = 0; j < 2; ++j) {
                int col = nt * 8 + qc * 2 + j;
                float bb = sb1[col], ww = sW2[col];
                p0 = fmaf(tanh_fast(acc[nt][j] + bb), ww, p0);
                p1 = fmaf(tanh_fast(acc[nt][2 + j] + bb), ww, p1);
            }
        }
        p0 += __shfl_xor_sync(0xFFFFFFFFu, p0, 1);
        p0 += __shfl_xor_sync(0xFFFFFFFFu, p0, 2);
        p1 += __shfl_xor_sync(0xFFFFFFFFu, p1, 1);
        p1 += __shfl_xor_sync(0xFFFFFFFFu, p1, 2);

        // ---- pool phase: read x (fp16) from the slab, no global traffic ----
        float4 accA = make_float4(0.f, 0.f, 0.f, 0.f);
        float4 accB = make_float4(0.f, 0.f, 0.f, 0.f);
        float wsum = 0.f;
        int curb = __ldg(&batch[rbase]);
        #pragma unroll
        for (int r = 0; r < 16; ++r) {
            float sc = (r < 8) ? __shfl_sync(0xFFFFFFFFu, p0, r * 4)
                               : __shfl_sync(0xFFFFFFFFu, p1, (r - 8) * 4);
            float wv = __expf(sc + b2v);
            int b = __ldg(&batch[rbase + r]);
            if (b != curb) {
                float* o = &out[curb * HID + l * 4];
                atomicAdd(o + 0, accA.x); atomicAdd(o + 1, accA.y);
                atomicAdd(o + 2, accA.z); atomicAdd(o + 3, accA.w);
                float* o2 = o + 128;
                atomicAdd(o2 + 0, accB.x); atomicAdd(o2 + 1, accB.y);
                atomicAdd(o2 + 2, accB.z); atomicAdd(o2 + 3, accB.w);
                if (l == 0) atomicAdd(&g_sw[curb], wsum);
                accA = make_float4(0.f, 0.f, 0.f, 0.f);
                accB = make_float4(0.f, 0.f, 0.f, 0.f);
                wsum = 0.f;
                curb = b;
            }
            wsum += wv;
            const uint32_t* row = Ah + r * A_PITCH;
            uint32_t pa0 = row[upool],      pa1 = row[upool + 1];
            uint32_t pb0 = row[64 + upool], pb1 = row[64 + upool + 1];
            float2 fa0 = __half22float2(*(__half2*)&pa0);
            float2 fa1 = __half22float2(*(__half2*)&pa1);
            float2 fb0 = __half22float2(*(__half2*)&pb0);
            float2 fb1 = __half22float2(*(__half2*)&pb1);
            accA.x = fmaf(fa0.x, wv, accA.x); accA.y = fmaf(fa0.y, wv, accA.y);
            accA.z = fmaf(fa1.x, wv, accA.z); accA.w = fmaf(fa1.y, wv, accA.w);
            accB.x = fmaf(fb0.x, wv, accB.x); accB.y = fmaf(fb0.y, wv, accB.y);
            accB.z = fmaf(fb1.x, wv, accB.z); accB.w = fmaf(fb1.y, wv, accB.w);
        }
        {
            float* o = &out[curb * HID + l * 4];
            atomicAdd(o + 0, accA.x); atomicAdd(o + 1, accA.y);
            atomicAdd(o + 2, accA.z); atomicAdd(o + 3, accA.w);
            float* o2 = o + 128;
            atomicAdd(o2 + 0, accB.x); atomicAdd(o2 + 1, accB.y);
            atomicAdd(o2 + 2, accB.z); atomicAdd(o2 + 3, accB.w);
            if (l == 0) atomicAdd(&g_sw[curb], wsum);
        }
    }
}

// ---------------- normalize: out[b][h] /= S[b] ----------------
__global__ void norm_kernel(float* __restrict__ out) {
    int i = blockIdx.x * blockDim.x + threadIdx.x;   // 0..262143
    float s = g_sw[i >> 8];
    float inv = (s > 0.f) ? __fdividef(1.f, s) : 0.f;
    out[i] *= inv;
}

extern "C" void kernel_launch(void* const* d_in, const int* in_sizes, int n_in,
                              void* d_out, int out_size) {
    const float* x     = (const float*)d_in[0];
    const int*   batch = (const int*)d_in[1];
    const float* W1    = (const float*)d_in[2];
    const float* b1    = (const float*)d_in[3];
    const float* W2    = (const float*)d_in[4];
    const float* b2    = (const float*)d_in[5];
    float* out = (float*)d_out;

    const int dyn = (A_OFF + 8 * A_SLAB) * 4;   // 65536 + 67584 = 133120 B
    cudaFuncSetAttribute(score_kernel, cudaFuncAttributeMaxDynamicSharedMemorySize, dyn);

    prep_kernel<<<16, 256>>>(W1);
    init_kernel<<<(NGRAPH * HID + 255) / 256, 256>>>(out);
    score_kernel<<<NSM, 256, dyn>>>(x, batch, b1, W2, b2, out);
    norm_kernel<<<NGRAPH * HID / 256, 256>>>(out);
}